// round 4
// baseline (speedup 1.0000x reference)
#include <cuda_runtime.h>
#include <math.h>

#define NLAB 17
#define LTOT 19
#define SEQ  256
#define MAXB 8192
#define WPB  4

__device__ int d_sorted[MAXB];   // row indices, descending length (rebuilt every call)

// half-lane h -> primary/secondary state.
// h 0-8:  dense singles O,B-P,S-P,B-O,S-O,B-L,S-L,B-M,S-M
// h 9-12: pairs (I-t in pA, E-t in pB), t = PER,ORG,LOC,MISC
// h 13-15: idle
__constant__ signed char cStateA[16] = {0,1,4,5,8,9,12,13,16, 2,6,10,14, 0,0,0};
__constant__ signed char cStateB[16] = {0,0,0,0,0,0,0,0,0,    3,7,11,15, 0,0,0};

// One block: histogram of lens + suffix scan (Hillis-Steele) + scatter into
// descending-length order. ~3us.
__global__ void crf_sched(const int* __restrict__ lens, int B)
{
    __shared__ int h[SEQ];
    __shared__ int s[SEQ];
    int t = threadIdx.x;
    h[t] = 0;
    __syncthreads();
    for (int i = t; i < B; i += SEQ) atomicAdd(&h[lens[i] - 1], 1);
    __syncthreads();
    s[t] = h[t];
    __syncthreads();
    #pragma unroll
    for (int o = 1; o < SEQ; o <<= 1) {
        int add = (t + o < SEQ) ? s[t + o] : 0;
        __syncthreads();
        s[t] += add;
        __syncthreads();
    }
    h[t] = s[t] - h[t];      // start cursor: #rows strictly longer
    __syncthreads();
    for (int i = t; i < B; i += SEQ) {
        int r = atomicAdd(&h[lens[i] - 1], 1);
        d_sorted[r] = i;
    }
}

// Two rows per warp (16-lane halves). Exp-domain forward, exact 2^-e rescale
// every 4 steps, 9 shuffles per step serve BOTH rows.
__global__ __launch_bounds__(32 * WPB)
void crf_fwd_kernel(const float* __restrict__ logits,
                    const int*   __restrict__ labels,
                    const int*   __restrict__ lens,
                    const float* __restrict__ transition,
                    float* __restrict__ out, int B)
{
    __shared__ float sT[LTOT * LTOT];
    for (int i = threadIdx.x; i < LTOT * LTOT; i += blockDim.x)
        sT[i] = transition[i];
    __syncthreads();

    const int lane = threadIdx.x & 31;
    const int warp = threadIdx.x >> 5;
    const int h    = lane & 15;
    const int base = lane & 16;

    const int nPairs = (B + 1) >> 1;
    const int rank = blockIdx.x + warp * gridDim.x;
    if (rank >= nPairs) return;

    const int iB   = 2 * rank + 1;
    const bool hasB = iB < B;
    const int bA = d_sorted[2 * rank];
    const int bB = hasB ? d_sorted[iB] : bA;
    const int b  = base ? bB : bA;
    const int len = lens[b];

    const float* lg  = logits + (size_t)b * (SEQ * NLAB);
    const int*   lab = labels + (size_t)b * SEQ;

    // ---------------- gold score (per half, parallel over t) ---------------
    float g = 0.f;
    for (int t = h; t < len; t += 16) {
        int lt = lab[t];
        int lp = (t == 0) ? (LTOT - 2) : lab[t - 1];
        g += lg[t * NLAB + lt] + sT[lt * LTOT + lp];
    }
    if (h == 0) g += sT[(LTOT - 1) * LTOT + lab[len - 1]];
    #pragma unroll
    for (int o = 8; o; o >>= 1) g += __shfl_xor_sync(0xffffffffu, g, o, 16);

    // ---------------- per-lane weights & shuffle sources --------------------
    const int sA = cStateA[h];
    const int sB = cStateB[h];
    const bool dense = (h <= 8);
    const bool pair  = (h >= 9) && (h <= 12);

    int srcA0, srcA1, srcA2, srcA3, srcA4, srcB0, srcB1, srcB2, srcB3;
    float wA0=0,wA1=0,wA2=0,wA3=0,wA4=0, wB0=0,wB1=0,wB2=0,wB3=0;
    float wE0=0, wE1=0, wstA=0, wstB=0, wenA=0, wenB=0;

    if (dense) {
        srcA0 = base + 0; srcA1 = base + 2; srcA2 = base + 4;
        srcA3 = base + 6; srcA4 = base + 8;
        srcB0 = base + 9; srcB1 = base + 10; srcB2 = base + 11; srcB3 = base + 12;
        wA0 = expf(sT[sA * LTOT + 0]);
        wA1 = expf(sT[sA * LTOT + 4]);
        wA2 = expf(sT[sA * LTOT + 8]);
        wA3 = expf(sT[sA * LTOT + 12]);
        wA4 = expf(sT[sA * LTOT + 16]);
        wB0 = expf(sT[sA * LTOT + 3]);
        wB1 = expf(sT[sA * LTOT + 7]);
        wB2 = expf(sT[sA * LTOT + 11]);
        wB3 = expf(sT[sA * LTOT + 15]);
        wstA = expf(sT[sA * LTOT + 17]);
        wenA = expf(sT[18 * LTOT + sA]);
    } else {
        srcA0 = base + (pair ? (1 + 2 * (h - 9)) : h);   // B-t holder lane
        srcA1 = base + h; srcA2 = base + h; srcA3 = base + h; srcA4 = base + h;
        srcB0 = base + h; srcB1 = base + h; srcB2 = base + h; srcB3 = base + h;
        if (pair) {
            int Bt = sA - 1;                 // B-t state
            wA0 = expf(sT[sA * LTOT + Bt]);  // I-t <- B-t
            wA1 = expf(sT[sA * LTOT + sA]);  // I-t <- I-t
            wE0 = expf(sT[sB * LTOT + Bt]);  // E-t <- B-t
            wE1 = expf(sT[sB * LTOT + sA]);  // E-t <- I-t
            wstA = expf(sT[sA * LTOT + 17]);
            wstB = expf(sT[sB * LTOT + 17]);
            wenA = expf(sT[18 * LTOT + sA]);
            wenB = expf(sT[18 * LTOT + sB]);
        }
    }

    const float* pAp = lg + sA;
    const float* pBp = lg + sB;

    // ---------------- t = 0 -------------------------------------------------
    float pA = __expf(pAp[0]) * wstA;
    float pB = __expf(pBp[0]) * wstB;
    int C = 0;
    {
        float m = fmaxf(pA, pB);
        #pragma unroll
        for (int o = 8; o; o >>= 1) m = fmaxf(m, __shfl_xor_sync(0xffffffffu, m, o, 16));
        int eb = (int)(__float_as_uint(m) >> 23);
        float sc = __uint_as_float((unsigned)(254 - eb) << 23);
        pA *= sc; pB *= sc; C += eb - 127;
    }

    const int lenO = __shfl_xor_sync(0xffffffffu, len, 16);
    const int wlen = max(len, lenO);

    float eAn = __expf(pAp[NLAB]);
    float eBn = __expf(pBp[NLAB]);
    const float* qA = pAp + 2 * NLAB;
    const float* qB = pBp + 2 * NLAB;

    // ---------------- forward recursion ------------------------------------
    for (int t = 1; t < wlen; ++t) {
        float eA = eAn, eB = eBn;
        if (t + 1 < SEQ) {
            eAn = __expf(*qA); qA += NLAB;
            eBn = __expf(*qB); qB += NLAB;
        }

        float g0 = __shfl_sync(0xffffffffu, pA, srcA0);
        float g1 = __shfl_sync(0xffffffffu, pA, srcA1);
        float g2 = __shfl_sync(0xffffffffu, pA, srcA2);
        float g3 = __shfl_sync(0xffffffffu, pA, srcA3);
        float g4 = __shfl_sync(0xffffffffu, pA, srcA4);
        float h0 = __shfl_sync(0xffffffffu, pB, srcB0);
        float h1 = __shfl_sync(0xffffffffu, pB, srcB1);
        float h2 = __shfl_sync(0xffffffffu, pB, srcB2);
        float h3 = __shfl_sync(0xffffffffu, pB, srcB3);

        float accB = fmaf(wE1, pA, wE0 * g0);   // E-t pre-sum (old pA)

        float a0 = wA0 * g0;
        float a1 = wA1 * g1;
        float a2 = wB0 * h0;
        a0 = fmaf(wA2, g2, a0);
        a1 = fmaf(wA3, g3, a1);
        a2 = fmaf(wB1, h1, a2);
        a0 = fmaf(wA4, g4, a0);
        a1 = fmaf(wB2, h2, a1);
        a2 = fmaf(wB3, h3, a2);
        float acc = (a0 + a1) + a2;

        bool act = t < len;
        pA = act ? eA * acc  : pA;
        pB = act ? eB * accB : pB;

        if ((t & 3) == 0) {                      // exact 2^-e rescale per half
            float m = fmaxf(pA, pB);
            #pragma unroll
            for (int o = 8; o; o >>= 1) m = fmaxf(m, __shfl_xor_sync(0xffffffffu, m, o, 16));
            int eb = (int)(__float_as_uint(m) >> 23);
            float sc = __uint_as_float((unsigned)(254 - eb) << 23);
            pA *= sc; pB *= sc; C += eb - 127;
        }
    }

    // ---------------- finalize ----------------------------------------------
    float s = fmaf(pA, wenA, pB * wenB);
    #pragma unroll
    for (int o = 8; o; o >>= 1) s += __shfl_xor_sync(0xffffffffu, s, o, 16);

    if (h == 0 && (base == 0 || hasB))
        out[b] = g - ((float)C * 0.69314718055994531f + logf(s));
}

extern "C" void kernel_launch(void* const* d_in, const int* in_sizes, int n_in,
                              void* d_out, int out_size)
{
    const float* logits     = (const float*)d_in[0];
    const int*   labels     = (const int*)  d_in[1];
    const int*   lens       = (const int*)  d_in[2];
    const float* transition = (const float*)d_in[3];
    float*       out        = (float*)d_out;

    int B = in_sizes[2];

    crf_sched<<<1, SEQ>>>(lens, B);

    int nPairs = (B + 1) / 2;
    int grid = (nPairs + WPB - 1) / WPB;
    crf_fwd_kernel<<<grid, 32 * WPB>>>(logits, labels, lens, transition, out, B);
}

// round 5
// speedup vs baseline: 1.1799x; 1.1799x over previous
#include <cuda_runtime.h>
#include <math.h>

#define NLAB 17
#define LTOT 19
#define SEQ  256
#define LN2  0.69314718055994531f

// Forward: predecessor lists per target state (pads -> col 18 = end col, T=-1e4 -> w=0)
__constant__ signed char PREDS[17][9] = {
  {0,3,4,7,8,11,12,15,16},
  {0,3,4,7,8,11,12,15,16},
  {1,2,18,18,18,18,18,18,18},
  {1,2,18,18,18,18,18,18,18},
  {0,3,4,7,8,11,12,15,16},
  {0,3,4,7,8,11,12,15,16},
  {5,6,18,18,18,18,18,18,18},
  {5,6,18,18,18,18,18,18,18},
  {0,3,4,7,8,11,12,15,16},
  {0,3,4,7,8,11,12,15,16},
  {9,10,18,18,18,18,18,18,18},
  {9,10,18,18,18,18,18,18,18},
  {0,3,4,7,8,11,12,15,16},
  {0,3,4,7,8,11,12,15,16},
  {13,14,18,18,18,18,18,18,18},
  {13,14,18,18,18,18,18,18,18},
  {0,3,4,7,8,11,12,15,16},
};

// Backward: successor lists per from-state (pads -> row 17 = start row, T=-1e4 -> w=0)
__constant__ signed char SUCCS[17][9] = {
  {0,1,4,5,8,9,12,13,16},
  {2,3,17,17,17,17,17,17,17},
  {2,3,17,17,17,17,17,17,17},
  {0,1,4,5,8,9,12,13,16},
  {0,1,4,5,8,9,12,13,16},
  {6,7,17,17,17,17,17,17,17},
  {6,7,17,17,17,17,17,17,17},
  {0,1,4,5,8,9,12,13,16},
  {0,1,4,5,8,9,12,13,16},
  {10,11,17,17,17,17,17,17,17},
  {10,11,17,17,17,17,17,17,17},
  {0,1,4,5,8,9,12,13,16},
  {0,1,4,5,8,9,12,13,16},
  {14,15,17,17,17,17,17,17,17},
  {14,15,17,17,17,17,17,17,17},
  {0,1,4,5,8,9,12,13,16},
  {0,1,4,5,8,9,12,13,16},
};

// Block = 8 warps = 4 rows. Warp 2r: forward half of row r; warp 2r+1: backward
// (adjoint) half. Meet at m=(len+1)/2, combine via smem + named barrier.
__global__ __launch_bounds__(256)
void crf_mitm_kernel(const float* __restrict__ logits,
                     const int*   __restrict__ labels,
                     const int*   __restrict__ lens,
                     const float* __restrict__ transition,
                     float* __restrict__ out, int B)
{
    __shared__ float sT[LTOT * LTOT];
    __shared__ float sA[4][18];   // [pair]: 0..16 = a vector, 17 = gold partial
    __shared__ int   sC[4];       // forward exponent counter

    for (int i = threadIdx.x; i < LTOT * LTOT; i += blockDim.x)
        sT[i] = transition[i];
    __syncthreads();

    const int lane = threadIdx.x & 31;
    const int warp = threadIdx.x >> 5;
    const int pairIdx = warp >> 1;
    const bool isBwd = warp & 1;

    const int row = blockIdx.x * 4 + pairIdx;
    if (row >= B) return;

    const int len = lens[row];
    const int m   = (len + 1) >> 1;

    const float* lg  = logits + (size_t)row * (SEQ * NLAB);
    const int*   lab = labels + (size_t)row * SEQ;
    const float* lgp = lg + ((lane < NLAB) ? lane : (NLAB - 1));  // clamped column

    const int barId = 1 + pairIdx;

    if (!isBwd) {
        // ================= FORWARD warp: a_{m-1}, gold over [0, m) ==========
        float g = 0.f;
        for (int t = lane; t < m; t += 32) {
            int lt = lab[t];
            int lp = (t == 0) ? (LTOT - 2) : lab[t - 1];
            g += lg[t * NLAB + lt] + sT[lt * LTOT + lp];
        }
        #pragma unroll
        for (int o = 16; o; o >>= 1) g += __shfl_xor_sync(0xffffffffu, g, o);

        float w[9]; int src[9];
        #pragma unroll
        for (int k = 0; k < 9; ++k) { w[k] = 0.f; src[k] = 18; }
        float wstart = 0.f;
        if (lane < NLAB) {
            #pragma unroll
            for (int k = 0; k < 9; ++k) {
                int pr = PREDS[lane][k];
                src[k] = pr;
                w[k]   = expf(sT[lane * LTOT + pr]);
            }
            wstart = expf(sT[lane * LTOT + 17]);
        }

        float p = __expf(lgp[0]) * wstart;
        int   C = 0;
        {
            unsigned mx = __reduce_max_sync(0xffffffffu, __float_as_uint(p));
            int eb = (int)(mx >> 23);
            p *= __uint_as_float((unsigned)(254 - eb) << 23);
            C += eb - 127;
        }
        const float* pf = lgp + NLAB;
        float enext = __expf(*pf);

        #pragma unroll 4
        for (int t = 1; t < m; ++t) {
            float ecur = enext;
            pf += NLAB;                      // t+1 <= m <= 128 : always in-bounds
            enext = __expf(*pf);

            float q0 = __shfl_sync(0xffffffffu, p, src[0]);
            float q1 = __shfl_sync(0xffffffffu, p, src[1]);
            float q2 = __shfl_sync(0xffffffffu, p, src[2]);
            float q3 = __shfl_sync(0xffffffffu, p, src[3]);
            float q4 = __shfl_sync(0xffffffffu, p, src[4]);
            float q5 = __shfl_sync(0xffffffffu, p, src[5]);
            float q6 = __shfl_sync(0xffffffffu, p, src[6]);
            float q7 = __shfl_sync(0xffffffffu, p, src[7]);
            float q8 = __shfl_sync(0xffffffffu, p, src[8]);

            float a0 = w[0] * q0;
            float a1 = w[1] * q1;
            float a2 = w[2] * q2;
            a0 = fmaf(w[3], q3, a0);
            a1 = fmaf(w[4], q4, a1);
            a2 = fmaf(w[5], q5, a2);
            a0 = fmaf(w[6], q6, a0);
            a1 = fmaf(w[7], q7, a1);
            a2 = fmaf(w[8], q8, a2);
            p = ecur * ((a0 + a1) + a2);

            if ((t & 3) == 0) {
                unsigned mx = __reduce_max_sync(0xffffffffu, __float_as_uint(p));
                int eb = (int)(mx >> 23);
                p *= __uint_as_float((unsigned)(254 - eb) << 23);
                C += eb - 127;
            }
        }

        if (lane < NLAB) sA[pairIdx][lane] = p;
        if (lane == 0) { sA[pairIdx][17] = g; sC[pairIdx] = C; }
        asm volatile("bar.sync %0, %1;" :: "r"(barId), "r"(64) : "memory");
        return;
    }

    // ================= BACKWARD warp: b_m, gold over [m, len) + end =========
    {
        float g = 0.f;
        for (int t = m + lane; t < len; t += 32) {
            int lt = lab[t];
            int lp = lab[t - 1];
            g += lg[t * NLAB + lt] + sT[lt * LTOT + lp];
        }
        if (lane == 0) g += sT[(LTOT - 1) * LTOT + lab[len - 1]];
        #pragma unroll
        for (int o = 16; o; o >>= 1) g += __shfl_xor_sync(0xffffffffu, g, o);

        float w[9]; int src[9];
        #pragma unroll
        for (int k = 0; k < 9; ++k) { w[k] = 0.f; src[k] = 17; }
        float bv = 0.f;
        if (lane < NLAB) {
            #pragma unroll
            for (int k = 0; k < 9; ++k) {
                int to = SUCCS[lane][k];
                src[k] = to;
                w[k]   = expf(sT[to * LTOT + lane]);   // pads: exp(-1e4) = 0
            }
            bv = expf(sT[18 * LTOT + lane]);           // w_end
        }

        int C = 0;
        const float* pf = lgp + (size_t)(len - 1) * NLAB;
        float enext = __expf(*pf);                     // d at t = len-1

        #pragma unroll 4
        for (int t = len - 1; t >= m; --t) {
            float d = enext;
            pf -= NLAB;                                // t-1 >= m-1 >= 0 : in-bounds
            enext = __expf(*pf);

            float u = bv * d;

            float q0 = __shfl_sync(0xffffffffu, u, src[0]);
            float q1 = __shfl_sync(0xffffffffu, u, src[1]);
            float q2 = __shfl_sync(0xffffffffu, u, src[2]);
            float q3 = __shfl_sync(0xffffffffu, u, src[3]);
            float q4 = __shfl_sync(0xffffffffu, u, src[4]);
            float q5 = __shfl_sync(0xffffffffu, u, src[5]);
            float q6 = __shfl_sync(0xffffffffu, u, src[6]);
            float q7 = __shfl_sync(0xffffffffu, u, src[7]);
            float q8 = __shfl_sync(0xffffffffu, u, src[8]);

            float a0 = w[0] * q0;
            float a1 = w[1] * q1;
            float a2 = w[2] * q2;
            a0 = fmaf(w[3], q3, a0);
            a1 = fmaf(w[4], q4, a1);
            a2 = fmaf(w[5], q5, a2);
            a0 = fmaf(w[6], q6, a0);
            a1 = fmaf(w[7], q7, a1);
            a2 = fmaf(w[8], q8, a2);
            bv = (a0 + a1) + a2;                       // lanes >= 17 stay 0

            if ((t & 3) == 0) {
                unsigned mx = __reduce_max_sync(0xffffffffu, __float_as_uint(bv));
                int eb = (int)(mx >> 23);
                bv *= __uint_as_float((unsigned)(254 - eb) << 23);
                C += eb - 127;
            }
        }

        asm volatile("bar.sync %0, %1;" :: "r"(barId), "r"(64) : "memory");

        float s = (lane < NLAB) ? bv * sA[pairIdx][lane] : 0.f;
        #pragma unroll
        for (int o = 16; o; o >>= 1) s += __shfl_xor_sync(0xffffffffu, s, o);

        if (lane == 0) {
            float gTot = g + sA[pairIdx][17];
            int   cTot = C + sC[pairIdx];
            out[row] = gTot - ((float)cTot * LN2 + logf(s));
        }
    }
}

extern "C" void kernel_launch(void* const* d_in, const int* in_sizes, int n_in,
                              void* d_out, int out_size)
{
    const float* logits     = (const float*)d_in[0];
    const int*   labels     = (const int*)  d_in[1];
    const int*   lens       = (const int*)  d_in[2];
    const float* transition = (const float*)d_in[3];
    float*       out        = (float*)d_out;

    int B = in_sizes[2];
    int grid = (B + 3) / 4;
    crf_mitm_kernel<<<grid, 256>>>(logits, labels, lens, transition, out, B);
}

// round 6
// speedup vs baseline: 1.7723x; 1.5021x over previous
#include <cuda_runtime.h>
#include <math.h>

#define NLAB 17
#define LTOT 19
#define SEQ  256
#define MAXB 8192
#define LN2  0.69314718055994531f
#define FULL 0xffffffffu

__device__ int d_sorted[MAXB];

// dense predecessor states (fwd gather): {O, E-*, S-*}
__constant__ signed char cDP[9] = {0,3,4,7,8,11,12,15,16};
// dense target states (bwd gather): {O, B-*, S-*}
__constant__ signed char cDT[9] = {0,1,4,5,8,9,12,13,16};

// One-block fused sort: histogram + Hillis-Steele suffix scan + scatter,
// d_sorted = row indices in descending length. (~1.3us measured)
__global__ void crf_sched(const int* __restrict__ lens, int B)
{
    __shared__ int h[SEQ];
    __shared__ int s[SEQ];
    int t = threadIdx.x;
    h[t] = 0;
    __syncthreads();
    for (int i = t; i < B; i += SEQ) atomicAdd(&h[lens[i] - 1], 1);
    __syncthreads();
    s[t] = h[t];
    __syncthreads();
    #pragma unroll
    for (int o = 1; o < SEQ; o <<= 1) {
        int add = (t + o < SEQ) ? s[t + o] : 0;
        __syncthreads();
        s[t] += add;
        __syncthreads();
    }
    h[t] = s[t] - h[t];
    __syncthreads();
    for (int i = t; i < B; i += SEQ) {
        int r = atomicAdd(&h[lens[i] - 1], 1);
        d_sorted[r] = i;
    }
}

#define RESC() { \
    float _mx = fmaxf(fmaxf(p0,p1), fmaxf(p2, fmaxf(p3,p4))); \
    _mx = fmaxf(_mx, __shfl_xor_sync(FULL,_mx,1,4)); \
    _mx = fmaxf(_mx, __shfl_xor_sync(FULL,_mx,2,4)); \
    int _eb = (int)(__float_as_uint(_mx)>>23); \
    float _sc = __uint_as_float((unsigned)(254-_eb)<<23); \
    p0*=_sc; p1*=_sc; p2*=_sc; p3*=_sc; p4*=_sc; C += _eb-127; }

#define FLOAD(R, T) { const float* _a = lp5 + (T)*NLAB; \
    R[0]=__ldg(_a+0); R[1]=__ldg(_a+1); R[2]=__ldg(_a+2); \
    R[3]=__ldg(_a+3); R[4]=__ldg(_a+4); }

#define BLOAD(R, K) { int _tt = lenm1 - (K); if (_tt < 0) _tt = 0; \
    const float* _a = lp5 + _tt*NLAB; \
    R[0]=__ldg(_a+0); R[1]=__ldg(_a+1); R[2]=__ldg(_a+2); \
    R[3]=__ldg(_a+3); R[4]=__ldg(_a+4); }

#define DENSE9() \
    float _S0=w0[0]*_Q0, _S1=w1[0]*_Q0, _S2=w2[0]*_Q0; \
    _S0=fmaf(w0[1],_Q1,_S0); _S1=fmaf(w1[1],_Q1,_S1); _S2=fmaf(w2[1],_Q1,_S2); \
    _S0=fmaf(w0[2],_Q2,_S0); _S1=fmaf(w1[2],_Q2,_S1); _S2=fmaf(w2[2],_Q2,_S2); \
    _S0=fmaf(w0[3],_Q3,_S0); _S1=fmaf(w1[3],_Q3,_S1); _S2=fmaf(w2[3],_Q3,_S2); \
    _S0=fmaf(w0[4],_Q4,_S0); _S1=fmaf(w1[4],_Q4,_S1); _S2=fmaf(w2[4],_Q4,_S2); \
    _S0=fmaf(w0[5],_Q5,_S0); _S1=fmaf(w1[5],_Q5,_S1); _S2=fmaf(w2[5],_Q5,_S2); \
    _S0=fmaf(w0[6],_Q6,_S0); _S1=fmaf(w1[6],_Q6,_S1); _S2=fmaf(w2[6],_Q6,_S2); \
    _S0=fmaf(w0[7],_Q7,_S0); _S1=fmaf(w1[7],_Q7,_S1); _S2=fmaf(w2[7],_Q7,_S2); \
    _S0=fmaf(w0[8],_Q8,_S0); _S1=fmaf(w1[8],_Q8,_S1); _S2=fmaf(w2[8],_Q8,_S2);

// forward step: p' = D_t * (E p); dense via gather of (p0,p3,p4@g3)
#define FSTEP(R, T) if ((T) < warpM) { \
    float _e0=__expf(R[0]), _e1=__expf(R[1]), _e2=__expf(R[2]); \
    float _e3=__expf(R[3]), _e4=__expf(R[4]); \
    float _Q0=__shfl_sync(FULL,p0,base+0); \
    float _Q1=__shfl_sync(FULL,p3,base+0); \
    float _Q2=__shfl_sync(FULL,p0,base+1); \
    float _Q3=__shfl_sync(FULL,p3,base+1); \
    float _Q4=__shfl_sync(FULL,p0,base+2); \
    float _Q5=__shfl_sync(FULL,p3,base+2); \
    float _Q6=__shfl_sync(FULL,p0,base+3); \
    float _Q7=__shfl_sync(FULL,p3,base+3); \
    float _Q8=__shfl_sync(FULL,p4,base+3); \
    DENSE9() \
    float _nI = fmaf(wII,p2, wIB*p1); \
    float _nE = fmaf(wEI,p2, wEB*p1); \
    bool _act = (T) < myM; \
    p0 = _act ? _e0*_S0 : p0; \
    p1 = _act ? _e1*_S1 : p1; \
    p2 = _act ? _e2*_nI : p2; \
    p3 = _act ? _e3*_nE : p3; \
    p4 = _act ? _e4*_S2 : p4; \
    if (((T)&3)==0) RESC() }

// backward step: u = b (.) d_t; b' = E^T u; dense via gather of (u0,u1,u4@g3)
#define BSTEP(R, K) if ((K) < warpS) { \
    float _u0=p0*__expf(R[0]); \
    float _u1=p1*__expf(R[1]); \
    float _u2=p2*__expf(R[2]); \
    float _u3=p3*__expf(R[3]); \
    float _u4=p4*__expf(R[4]); \
    float _Q0=__shfl_sync(FULL,_u0,base+0); \
    float _Q1=__shfl_sync(FULL,_u1,base+0); \
    float _Q2=__shfl_sync(FULL,_u0,base+1); \
    float _Q3=__shfl_sync(FULL,_u1,base+1); \
    float _Q4=__shfl_sync(FULL,_u0,base+2); \
    float _Q5=__shfl_sync(FULL,_u1,base+2); \
    float _Q6=__shfl_sync(FULL,_u0,base+3); \
    float _Q7=__shfl_sync(FULL,_u1,base+3); \
    float _Q8=__shfl_sync(FULL,_u4,base+3); \
    DENSE9() \
    float _nB = fmaf(wEB,_u3, wIB*_u2); \
    float _nI = fmaf(wEI,_u3, wII*_u2); \
    bool _act = (K) < mySteps; \
    p0 = _act ? _S0 : p0; \
    p1 = _act ? _nB : p1; \
    p2 = _act ? _nI : p2; \
    p3 = _act ? _S1 : p3; \
    p4 = _act ? _S2 : p4; \
    if (((K)&3)==3) RESC() }

// Block = 8 warps = 4 (fwd,bwd) pairs, 8 rows per pair (4 lanes per row).
// Lane g owns states 4g..4g+3 (+16 on g=3). Meet-in-the-middle at m=ceil(len/2).
__global__ __launch_bounds__(256)
void crf_main(const float* __restrict__ logits,
              const int*   __restrict__ labels,
              const int*   __restrict__ lens,
              const float* __restrict__ transition,
              float* __restrict__ out, int B)
{
    __shared__ float sT[LTOT*LTOT];
    __shared__ float sA[4][8][20];
    __shared__ float sG[4][8];
    __shared__ int   sC[4][8];

    for (int i = threadIdx.x; i < LTOT*LTOT; i += 256) sT[i] = transition[i];
    __syncthreads();

    const int lane = threadIdx.x & 31;
    const int wId  = threadIdx.x >> 5;
    const int q    = wId >> 1;
    const bool isB = wId & 1;
    const int g    = lane & 3;
    const int r    = lane >> 2;
    const int base = lane & ~3;

    int rank = (blockIdx.x*4 + q)*8 + r;
    const bool valid = rank < B;
    if (!valid) rank = B - 1;
    const int b   = d_sorted[rank];
    const int len = lens[b];
    const int m   = (len + 1) >> 1;

    const float* lg  = logits + (size_t)b * (SEQ*NLAB);
    const int*   lab = labels + (size_t)b * SEQ;
    const int    s0  = 4*g;
    const float* lp5 = lg + s0;

    float p0,p1,p2,p3,p4;
    int C = 0;
    float gold = 0.f;

    if (!isB) {
        // ---------------- FORWARD: a_{m-1}, gold over [0,m) ----------------
        for (int t = g; t < m; t += 4) {
            int lt = lab[t];
            int lp = (t == 0) ? (LTOT-2) : lab[t-1];
            gold += lg[t*NLAB + lt] + sT[lt*LTOT + lp];
        }
        gold += __shfl_xor_sync(FULL, gold, 1, 4);
        gold += __shfl_xor_sync(FULL, gold, 2, 4);

        float w0[9], w1[9], w2[9];
        #pragma unroll
        for (int k = 0; k < 9; ++k) {
            int pr = cDP[k];
            w0[k] = expf(sT[s0*LTOT + pr]);            // target 4g   (O/S-*)
            w1[k] = expf(sT[(s0+1)*LTOT + pr]);        // target 4g+1 (B-*)
            w2[k] = (g==3) ? expf(sT[16*LTOT + pr]) : 0.f;  // target 16 (S-M)
        }
        const float wIB = expf(sT[(s0+2)*LTOT + (s0+1)]);
        const float wII = expf(sT[(s0+2)*LTOT + (s0+2)]);
        const float wEB = expf(sT[(s0+3)*LTOT + (s0+1)]);
        const float wEI = expf(sT[(s0+3)*LTOT + (s0+2)]);

        {   // t = 0
            float wst4 = (g==3) ? expf(sT[16*LTOT + 17]) : 0.f;
            p0 = __expf(__ldg(lp5+0)) * expf(sT[s0*LTOT + 17]);
            p1 = __expf(__ldg(lp5+1)) * expf(sT[(s0+1)*LTOT + 17]);
            p2 = __expf(__ldg(lp5+2)) * expf(sT[(s0+2)*LTOT + 17]);
            p3 = __expf(__ldg(lp5+3)) * expf(sT[(s0+3)*LTOT + 17]);
            p4 = __expf(__ldg(lp5+4)) * wst4;
            RESC()
        }

        const int myM   = m;
        const int warpM = __reduce_max_sync(FULL, myM);

        float RA[4][5], RB[4][5];
        FLOAD(RA[0],1) FLOAD(RA[1],2) FLOAD(RA[2],3) FLOAD(RA[3],4)
        for (int t0 = 1; t0 < warpM; t0 += 8) {
            FLOAD(RB[0],t0+4) FLOAD(RB[1],t0+5) FLOAD(RB[2],t0+6) FLOAD(RB[3],t0+7)
            FSTEP(RA[0],t0) FSTEP(RA[1],t0+1) FSTEP(RA[2],t0+2) FSTEP(RA[3],t0+3)
            FLOAD(RA[0],t0+8) FLOAD(RA[1],t0+9) FLOAD(RA[2],t0+10) FLOAD(RA[3],t0+11)
            FSTEP(RB[0],t0+4) FSTEP(RB[1],t0+5) FSTEP(RB[2],t0+6) FSTEP(RB[3],t0+7)
        }

        sA[q][r][s0+0]=p0; sA[q][r][s0+1]=p1;
        sA[q][r][s0+2]=p2; sA[q][r][s0+3]=p3;
        if (g==3) sA[q][r][16]=p4;
        if (g==0) { sG[q][r]=gold; sC[q][r]=C; }
        asm volatile("bar.sync %0, %1;" :: "r"(1+q), "r"(64) : "memory");
    } else {
        // ---------------- BACKWARD: b_m, gold over [m,len) + end ----------
        for (int t = m + g; t < len; t += 4) {
            int lt = lab[t];
            gold += lg[t*NLAB + lt] + sT[lt*LTOT + lab[t-1]];
        }
        if (g==0) gold += sT[(LTOT-1)*LTOT + lab[len-1]];
        gold += __shfl_xor_sync(FULL, gold, 1, 4);
        gold += __shfl_xor_sync(FULL, gold, 2, 4);

        float w0[9], w1[9], w2[9];
        #pragma unroll
        for (int k = 0; k < 9; ++k) {
            int dt = cDT[k];
            w0[k] = expf(sT[dt*LTOT + s0]);            // source 4g   (O/S-*)
            w1[k] = expf(sT[dt*LTOT + (s0+3)]);        // source 4g+3 (E-*)
            w2[k] = (g==3) ? expf(sT[dt*LTOT + 16]) : 0.f;  // source 16 (S-M)
        }
        const float wIB = expf(sT[(s0+2)*LTOT + (s0+1)]);
        const float wII = expf(sT[(s0+2)*LTOT + (s0+2)]);
        const float wEB = expf(sT[(s0+3)*LTOT + (s0+1)]);
        const float wEI = expf(sT[(s0+3)*LTOT + (s0+2)]);

        p0 = expf(sT[18*LTOT + s0]);
        p1 = expf(sT[18*LTOT + (s0+1)]);
        p2 = expf(sT[18*LTOT + (s0+2)]);
        p3 = expf(sT[18*LTOT + (s0+3)]);
        p4 = (g==3) ? expf(sT[18*LTOT + 16]) : 0.f;

        const int mySteps = len - m;
        const int warpS   = __reduce_max_sync(FULL, mySteps);
        const int lenm1   = len - 1;

        float RA[4][5], RB[4][5];
        BLOAD(RA[0],0) BLOAD(RA[1],1) BLOAD(RA[2],2) BLOAD(RA[3],3)
        for (int k0 = 0; k0 < warpS; k0 += 8) {
            BLOAD(RB[0],k0+4) BLOAD(RB[1],k0+5) BLOAD(RB[2],k0+6) BLOAD(RB[3],k0+7)
            BSTEP(RA[0],k0) BSTEP(RA[1],k0+1) BSTEP(RA[2],k0+2) BSTEP(RA[3],k0+3)
            BLOAD(RA[0],k0+8) BLOAD(RA[1],k0+9) BLOAD(RA[2],k0+10) BLOAD(RA[3],k0+11)
            BSTEP(RB[0],k0+4) BSTEP(RB[1],k0+5) BSTEP(RB[2],k0+6) BSTEP(RB[3],k0+7)
        }

        asm volatile("bar.sync %0, %1;" :: "r"(1+q), "r"(64) : "memory");

        float ss = p0 * sA[q][r][s0+0];
        ss = fmaf(p1, sA[q][r][s0+1], ss);
        ss = fmaf(p2, sA[q][r][s0+2], ss);
        ss = fmaf(p3, sA[q][r][s0+3], ss);
        ss = fmaf(p4, sA[q][r][s0+4], ss);   // g<3: p4==0, slot harmless
        ss += __shfl_xor_sync(FULL, ss, 1, 4);
        ss += __shfl_xor_sync(FULL, ss, 2, 4);

        if (g==0 && valid) {
            float gT = gold + sG[q][r];
            int   cT = C + sC[q][r];
            out[b] = gT - ((float)cT*LN2 + logf(ss));
        }
    }
}

extern "C" void kernel_launch(void* const* d_in, const int* in_sizes, int n_in,
                              void* d_out, int out_size)
{
    const float* logits     = (const float*)d_in[0];
    const int*   labels     = (const int*)  d_in[1];
    const int*   lens       = (const int*)  d_in[2];
    const float* transition = (const float*)d_in[3];
    float*       out        = (float*)d_out;

    int B = in_sizes[2];

    crf_sched<<<1, SEQ>>>(lens, B);

    int grid = (B + 31) / 32;
    crf_main<<<grid, 256>>>(logits, labels, lens, transition, out, B);
}

// round 7
// speedup vs baseline: 2.2636x; 1.2772x over previous
#include <cuda_runtime.h>
#include <math.h>

#define NLAB 17
#define LTOT 19
#define SEQ  256
#define MAXB 8192
#define LN2  0.69314718055994531f
#define FULL 0xffffffffu

__device__ int d_sorted[MAXB];

// dense predecessor states (fwd gather): {O, E-*, S-*}
__constant__ signed char cDP[9] = {0,3,4,7,8,11,12,15,16};
// dense target states (bwd gather): {O, B-*, S-*}
__constant__ signed char cDT[9] = {0,1,4,5,8,9,12,13,16};

// One-block fused sort: histogram + Hillis-Steele suffix scan + scatter,
// d_sorted = row indices in descending length.
__global__ void crf_sched(const int* __restrict__ lens, int B)
{
    __shared__ int h[SEQ];
    __shared__ int s[SEQ];
    int t = threadIdx.x;
    h[t] = 0;
    __syncthreads();
    for (int i = t; i < B; i += SEQ) atomicAdd(&h[lens[i] - 1], 1);
    __syncthreads();
    s[t] = h[t];
    __syncthreads();
    #pragma unroll
    for (int o = 1; o < SEQ; o <<= 1) {
        int add = (t + o < SEQ) ? s[t + o] : 0;
        __syncthreads();
        s[t] += add;
        __syncthreads();
    }
    h[t] = s[t] - h[t];
    __syncthreads();
    for (int i = t; i < B; i += SEQ) {
        int r = atomicAdd(&h[lens[i] - 1], 1);
        d_sorted[r] = i;
    }
}

#define RESC() { \
    float _mx = fmaxf(fmaxf(p0,p1), fmaxf(p2, fmaxf(p3,p4))); \
    _mx = fmaxf(_mx, __shfl_xor_sync(FULL,_mx,1,4)); \
    _mx = fmaxf(_mx, __shfl_xor_sync(FULL,_mx,2,4)); \
    int _eb = (int)(__float_as_uint(_mx)>>23); \
    float _sc = __uint_as_float((unsigned)(254-_eb)<<23); \
    p0*=_sc; p1*=_sc; p2*=_sc; p3*=_sc; p4*=_sc; C += _eb-127; }

#define FLOAD(R, T) { const float* _a = lp5 + (T)*NLAB; \
    R[0]=__ldg(_a+0); R[1]=__ldg(_a+1); R[2]=__ldg(_a+2); \
    R[3]=__ldg(_a+3); R[4]=__ldg(_a+4); }

#define BLOAD(R, K) { int _tt = lenm1 - (K); if (_tt < 0) _tt = 0; \
    const float* _a = lp5 + _tt*NLAB; \
    R[0]=__ldg(_a+0); R[1]=__ldg(_a+1); R[2]=__ldg(_a+2); \
    R[3]=__ldg(_a+3); R[4]=__ldg(_a+4); }

#define DENSE9() \
    float _S0=w0[0]*_Q0, _S1=w1[0]*_Q0, _S2=w2[0]*_Q0; \
    _S0=fmaf(w0[1],_Q1,_S0); _S1=fmaf(w1[1],_Q1,_S1); _S2=fmaf(w2[1],_Q1,_S2); \
    _S0=fmaf(w0[2],_Q2,_S0); _S1=fmaf(w1[2],_Q2,_S1); _S2=fmaf(w2[2],_Q2,_S2); \
    _S0=fmaf(w0[3],_Q3,_S0); _S1=fmaf(w1[3],_Q3,_S1); _S2=fmaf(w2[3],_Q3,_S2); \
    _S0=fmaf(w0[4],_Q4,_S0); _S1=fmaf(w1[4],_Q4,_S1); _S2=fmaf(w2[4],_Q4,_S2); \
    _S0=fmaf(w0[5],_Q5,_S0); _S1=fmaf(w1[5],_Q5,_S1); _S2=fmaf(w2[5],_Q5,_S2); \
    _S0=fmaf(w0[6],_Q6,_S0); _S1=fmaf(w1[6],_Q6,_S1); _S2=fmaf(w2[6],_Q6,_S2); \
    _S0=fmaf(w0[7],_Q7,_S0); _S1=fmaf(w1[7],_Q7,_S1); _S2=fmaf(w2[7],_Q7,_S2); \
    _S0=fmaf(w0[8],_Q8,_S0); _S1=fmaf(w1[8],_Q8,_S1); _S2=fmaf(w2[8],_Q8,_S2);

#define FSTEP(R, T) if ((T) < warpM) { \
    float _e0=__expf(R[0]), _e1=__expf(R[1]), _e2=__expf(R[2]); \
    float _e3=__expf(R[3]), _e4=__expf(R[4]); \
    float _Q0=__shfl_sync(FULL,p0,base+0); \
    float _Q1=__shfl_sync(FULL,p3,base+0); \
    float _Q2=__shfl_sync(FULL,p0,base+1); \
    float _Q3=__shfl_sync(FULL,p3,base+1); \
    float _Q4=__shfl_sync(FULL,p0,base+2); \
    float _Q5=__shfl_sync(FULL,p3,base+2); \
    float _Q6=__shfl_sync(FULL,p0,base+3); \
    float _Q7=__shfl_sync(FULL,p3,base+3); \
    float _Q8=__shfl_sync(FULL,p4,base+3); \
    DENSE9() \
    float _nI = fmaf(wII,p2, wIB*p1); \
    float _nE = fmaf(wEI,p2, wEB*p1); \
    bool _act = (T) < myM; \
    p0 = _act ? _e0*_S0 : p0; \
    p1 = _act ? _e1*_S1 : p1; \
    p2 = _act ? _e2*_nI : p2; \
    p3 = _act ? _e3*_nE : p3; \
    p4 = _act ? _e4*_S2 : p4; \
    if (((T)&3)==0) RESC() }

#define BSTEP(R, K) if ((K) < warpS) { \
    float _u0=p0*__expf(R[0]); \
    float _u1=p1*__expf(R[1]); \
    float _u2=p2*__expf(R[2]); \
    float _u3=p3*__expf(R[3]); \
    float _u4=p4*__expf(R[4]); \
    float _Q0=__shfl_sync(FULL,_u0,base+0); \
    float _Q1=__shfl_sync(FULL,_u1,base+0); \
    float _Q2=__shfl_sync(FULL,_u0,base+1); \
    float _Q3=__shfl_sync(FULL,_u1,base+1); \
    float _Q4=__shfl_sync(FULL,_u0,base+2); \
    float _Q5=__shfl_sync(FULL,_u1,base+2); \
    float _Q6=__shfl_sync(FULL,_u0,base+3); \
    float _Q7=__shfl_sync(FULL,_u1,base+3); \
    float _Q8=__shfl_sync(FULL,_u4,base+3); \
    DENSE9() \
    float _nB = fmaf(wEB,_u3, wIB*_u2); \
    float _nI = fmaf(wEI,_u3, wII*_u2); \
    bool _act = (K) < mySteps; \
    p0 = _act ? _S0 : p0; \
    p1 = _act ? _nB : p1; \
    p2 = _act ? _nI : p2; \
    p3 = _act ? _S1 : p3; \
    p4 = _act ? _S2 : p4; \
    if (((K)&3)==3) RESC() }

// Block = 8 warps = 4 (fwd,bwd) pairs, 8 rows per pair (4 lanes per row).
// Serpentine group assignment: pair q of block b handles sorted group
// G = q*gridDim + (b or gridDim-1-b), so every block's 4 pairs sample the
// length distribution evenly -> balanced per-SM makespan, all SMs busy.
__global__ __launch_bounds__(256)
void crf_main(const float* __restrict__ logits,
              const int*   __restrict__ labels,
              const int*   __restrict__ lens,
              const float* __restrict__ transition,
              float* __restrict__ out, int B)
{
    __shared__ float sT[LTOT*LTOT];
    __shared__ float sA[4][8][20];
    __shared__ float sG[4][8];
    __shared__ int   sC[4][8];

    for (int i = threadIdx.x; i < LTOT*LTOT; i += 256) sT[i] = transition[i];
    __syncthreads();

    const int lane = threadIdx.x & 31;
    const int wId  = threadIdx.x >> 5;
    const int q    = wId >> 1;
    const bool isB = wId & 1;
    const int g    = lane & 3;
    const int r    = lane >> 2;
    const int base = lane & ~3;

    const int nG  = (B + 7) >> 3;
    const int per = gridDim.x;
    const int G   = q * per + ((q & 1) ? (per - 1 - (int)blockIdx.x)
                                       : (int)blockIdx.x);
    int rank = G * 8 + r;
    const bool valid = (G < nG) && (rank < B);
    if (!valid) rank = B - 1;
    const int b   = d_sorted[rank];
    const int len = lens[b];
    const int m   = (len + 1) >> 1;

    const float* lg  = logits + (size_t)b * (SEQ*NLAB);
    const int*   lab = labels + (size_t)b * SEQ;
    const int    s0  = 4*g;
    const float* lp5 = lg + s0;

    float p0,p1,p2,p3,p4;
    int C = 0;
    float gold = 0.f;

    if (!isB) {
        // ---------------- FORWARD: a_{m-1}, gold over [0,m) ----------------
        for (int t = g; t < m; t += 4) {
            int lt = lab[t];
            int lp = (t == 0) ? (LTOT-2) : lab[t-1];
            gold += lg[t*NLAB + lt] + sT[lt*LTOT + lp];
        }
        gold += __shfl_xor_sync(FULL, gold, 1, 4);
        gold += __shfl_xor_sync(FULL, gold, 2, 4);

        float w0[9], w1[9], w2[9];
        #pragma unroll
        for (int k = 0; k < 9; ++k) {
            int pr = cDP[k];
            w0[k] = expf(sT[s0*LTOT + pr]);
            w1[k] = expf(sT[(s0+1)*LTOT + pr]);
            w2[k] = (g==3) ? expf(sT[16*LTOT + pr]) : 0.f;
        }
        const float wIB = expf(sT[(s0+2)*LTOT + (s0+1)]);
        const float wII = expf(sT[(s0+2)*LTOT + (s0+2)]);
        const float wEB = expf(sT[(s0+3)*LTOT + (s0+1)]);
        const float wEI = expf(sT[(s0+3)*LTOT + (s0+2)]);

        {   // t = 0
            float wst4 = (g==3) ? expf(sT[16*LTOT + 17]) : 0.f;
            p0 = __expf(__ldg(lp5+0)) * expf(sT[s0*LTOT + 17]);
            p1 = __expf(__ldg(lp5+1)) * expf(sT[(s0+1)*LTOT + 17]);
            p2 = __expf(__ldg(lp5+2)) * expf(sT[(s0+2)*LTOT + 17]);
            p3 = __expf(__ldg(lp5+3)) * expf(sT[(s0+3)*LTOT + 17]);
            p4 = __expf(__ldg(lp5+4)) * wst4;
            RESC()
        }

        const int myM   = m;
        const int warpM = __reduce_max_sync(FULL, myM);

        float RA[4][5], RB[4][5];
        FLOAD(RA[0],1) FLOAD(RA[1],2) FLOAD(RA[2],3) FLOAD(RA[3],4)
        for (int t0 = 1; t0 < warpM; t0 += 8) {
            FLOAD(RB[0],t0+4) FLOAD(RB[1],t0+5) FLOAD(RB[2],t0+6) FLOAD(RB[3],t0+7)
            FSTEP(RA[0],t0) FSTEP(RA[1],t0+1) FSTEP(RA[2],t0+2) FSTEP(RA[3],t0+3)
            FLOAD(RA[0],t0+8) FLOAD(RA[1],t0+9) FLOAD(RA[2],t0+10) FLOAD(RA[3],t0+11)
            FSTEP(RB[0],t0+4) FSTEP(RB[1],t0+5) FSTEP(RB[2],t0+6) FSTEP(RB[3],t0+7)
        }

        sA[q][r][s0+0]=p0; sA[q][r][s0+1]=p1;
        sA[q][r][s0+2]=p2; sA[q][r][s0+3]=p3;
        if (g==3) sA[q][r][16]=p4;
        if (g==0) { sG[q][r]=gold; sC[q][r]=C; }
        asm volatile("bar.sync %0, %1;" :: "r"(1+q), "r"(64) : "memory");
    } else {
        // ---------------- BACKWARD: b_m, gold over [m,len) + end ----------
        for (int t = m + g; t < len; t += 4) {
            int lt = lab[t];
            gold += lg[t*NLAB + lt] + sT[lt*LTOT + lab[t-1]];
        }
        if (g==0) gold += sT[(LTOT-1)*LTOT + lab[len-1]];
        gold += __shfl_xor_sync(FULL, gold, 1, 4);
        gold += __shfl_xor_sync(FULL, gold, 2, 4);

        float w0[9], w1[9], w2[9];
        #pragma unroll
        for (int k = 0; k < 9; ++k) {
            int dt = cDT[k];
            w0[k] = expf(sT[dt*LTOT + s0]);
            w1[k] = expf(sT[dt*LTOT + (s0+3)]);
            w2[k] = (g==3) ? expf(sT[dt*LTOT + 16]) : 0.f;
        }
        const float wIB = expf(sT[(s0+2)*LTOT + (s0+1)]);
        const float wII = expf(sT[(s0+2)*LTOT + (s0+2)]);
        const float wEB = expf(sT[(s0+3)*LTOT + (s0+1)]);
        const float wEI = expf(sT[(s0+3)*LTOT + (s0+2)]);

        p0 = expf(sT[18*LTOT + s0]);
        p1 = expf(sT[18*LTOT + (s0+1)]);
        p2 = expf(sT[18*LTOT + (s0+2)]);
        p3 = expf(sT[18*LTOT + (s0+3)]);
        p4 = (g==3) ? expf(sT[18*LTOT + 16]) : 0.f;

        const int mySteps = len - m;
        const int warpS   = __reduce_max_sync(FULL, mySteps);
        const int lenm1   = len - 1;

        float RA[4][5], RB[4][5];
        BLOAD(RA[0],0) BLOAD(RA[1],1) BLOAD(RA[2],2) BLOAD(RA[3],3)
        for (int k0 = 0; k0 < warpS; k0 += 8) {
            BLOAD(RB[0],k0+4) BLOAD(RB[1],k0+5) BLOAD(RB[2],k0+6) BLOAD(RB[3],k0+7)
            BSTEP(RA[0],k0) BSTEP(RA[1],k0+1) BSTEP(RA[2],k0+2) BSTEP(RA[3],k0+3)
            BLOAD(RA[0],k0+8) BLOAD(RA[1],k0+9) BLOAD(RA[2],k0+10) BLOAD(RA[3],k0+11)
            BSTEP(RB[0],k0+4) BSTEP(RB[1],k0+5) BSTEP(RB[2],k0+6) BSTEP(RB[3],k0+7)
        }

        asm volatile("bar.sync %0, %1;" :: "r"(1+q), "r"(64) : "memory");

        float ss = p0 * sA[q][r][s0+0];
        ss = fmaf(p1, sA[q][r][s0+1], ss);
        ss = fmaf(p2, sA[q][r][s0+2], ss);
        ss = fmaf(p3, sA[q][r][s0+3], ss);
        ss = fmaf(p4, sA[q][r][s0+4], ss);
        ss += __shfl_xor_sync(FULL, ss, 1, 4);
        ss += __shfl_xor_sync(FULL, ss, 2, 4);

        if (g==0 && valid) {
            float gT = gold + sG[q][r];
            int   cT = C + sC[q][r];
            out[b] = gT - ((float)cT*LN2 + logf(ss));
        }
    }
}

extern "C" void kernel_launch(void* const* d_in, const int* in_sizes, int n_in,
                              void* d_out, int out_size)
{
    const float* logits     = (const float*)d_in[0];
    const int*   labels     = (const int*)  d_in[1];
    const int*   lens       = (const int*)  d_in[2];
    const float* transition = (const float*)d_in[3];
    float*       out        = (float*)d_out;

    int B = in_sizes[2];

    crf_sched<<<1, SEQ>>>(lens, B);

    int nGroups = (B + 7) / 8;
    int grid = (nGroups + 3) / 4;
    if (grid < 148) grid = 148;       // one block per SM, serpentine fills it
    crf_main<<<grid, 256>>>(logits, labels, lens, transition, out, B);
}